// round 13
// baseline (speedup 1.0000x reference)
#include <cuda_runtime.h>
#include <cuda_fp16.h>
#include <cstdint>

#define N_NODES 100000
#define N_EDGES 640000
#define D 128
#define R 4
#define LRELU_ALPHA 0.2f

#define NR (N_NODES * R)
#define NRD ((size_t)N_NODES * R * D)

// ---------------- scratch ----------------
__device__ __align__(16) __half   g_A[NRD];
__device__ __align__(16) __half   g_B[NRD];
__device__ __align__(16) float    g_G[NRD];
__device__             float    g_denom[NR];
__device__ __align__(16) float    g_wqk[R * D];
__device__             float    g_c[R];

// ---------------- helpers ----------------
__device__ __forceinline__ float lrelu(float v) { return v > 0.f ? v : LRELU_ALPHA * v; }
__device__ __forceinline__ uint32_t smem_u32(const void* p) {
    uint32_t a;
    asm("{ .reg .u64 t; cvta.to.shared.u64 t, %1; cvt.u32.u64 %0, t; }" : "=r"(a) : "l"(p));
    return a;
}

// ---------------- mma.sync primitives ----------------
__device__ __forceinline__ void ldsm4(uint32_t* r, uint32_t a) {
    asm volatile("ldmatrix.sync.aligned.m8n8.x4.shared.b16 {%0,%1,%2,%3}, [%4];"
                 : "=r"(r[0]), "=r"(r[1]), "=r"(r[2]), "=r"(r[3]) : "r"(a));
}
__device__ __forceinline__ void ldsm4t(uint32_t* r, uint32_t a) {
    asm volatile("ldmatrix.sync.aligned.m8n8.x4.trans.shared.b16 {%0,%1,%2,%3}, [%4];"
                 : "=r"(r[0]), "=r"(r[1]), "=r"(r[2]), "=r"(r[3]) : "r"(a));
}
__device__ __forceinline__ void mma16816(float* d, const uint32_t* a, const uint32_t* b) {
    asm volatile(
        "mma.sync.aligned.m16n8k16.row.col.f32.f16.f16.f32 "
        "{%0,%1,%2,%3}, {%4,%5,%6,%7}, {%8,%9}, {%0,%1,%2,%3};"
        : "+f"(d[0]), "+f"(d[1]), "+f"(d[2]), "+f"(d[3])
        : "r"(a[0]), "r"(a[1]), "r"(a[2]), "r"(a[3]), "r"(b[0]), "r"(b[1]));
}

#define ROWB 272
#define TILE_BYTES (128 * ROWB)
#define GTILE_BYTES (64 * ROWB)
#define GEMM_SMEM (GTILE_BYTES + TILE_BYTES)  // x64 + W (52.2 KB -> 4 CTAs/SM)
#define FINAL_SMEM (GTILE_BYTES + TILE_BYTES) // g64 + W

// stage a 128x128 fp32 tile into single fp16 smem buffer (with row bound)
__device__ __forceinline__ void stage_f16(uint32_t dstb, const float* __restrict__ src,
                                          size_t row_stride, int valid_rows, int t) {
#pragma unroll
    for (int i = 0; i < 16; i++) {
        int lin = (i * 256 + t) * 4;
        int row = lin >> 7, col = lin & 127;
        float4 v = make_float4(0.f, 0.f, 0.f, 0.f);
        if (row < valid_rows) v = *(const float4*)(src + (size_t)row * row_stride + col);
        uint32_t off = (uint32_t)row * ROWB + (uint32_t)col * 2;
        __half h0 = __float2half_rn(v.x), h1 = __float2half_rn(v.y);
        __half h2 = __float2half_rn(v.z), h3 = __float2half_rn(v.w);
        uint32_t a = (uint32_t)__half_as_ushort(h0) | ((uint32_t)__half_as_ushort(h1) << 16);
        uint32_t b = (uint32_t)__half_as_ushort(h2) | ((uint32_t)__half_as_ushort(h3) << 16);
        asm volatile("st.shared.v2.u32 [%0], {%1,%2};" :: "r"(dstb + off), "r"(a), "r"(b));
    }
}

// stage 64x128 fp32 rows into fp16 buffer (no scaling)
__device__ __forceinline__ void stage_x64(uint32_t dstb, const float* __restrict__ src,
                                          size_t row_stride, int valid_rows, int t) {
#pragma unroll
    for (int i = 0; i < 8; i++) {
        int lin = (i * 256 + t) * 4;
        int row = lin >> 7, col = lin & 127;
        float4 v = make_float4(0.f, 0.f, 0.f, 0.f);
        if (row < valid_rows) v = *(const float4*)(src + (size_t)row * row_stride + col);
        uint32_t off = (uint32_t)row * ROWB + (uint32_t)col * 2;
        __half h0 = __float2half_rn(v.x), h1 = __float2half_rn(v.y);
        __half h2 = __float2half_rn(v.z), h3 = __float2half_rn(v.w);
        uint32_t a = (uint32_t)__half_as_ushort(h0) | ((uint32_t)__half_as_ushort(h1) << 16);
        uint32_t b = (uint32_t)__half_as_ushort(h2) | ((uint32_t)__half_as_ushort(h3) << 16);
        asm volatile("st.shared.v2.u32 [%0], {%1,%2};" :: "r"(dstb + off), "r"(a), "r"(b));
    }
}

// stage 64x128 G rows scaled by 1/denom into fp16 buffer
__device__ __forceinline__ void stage_g64(uint32_t dstb, const float* __restrict__ src,
                                          size_t row_stride, int valid_rows, int t,
                                          int nb, int r) {
#pragma unroll
    for (int i = 0; i < 8; i++) {
        int lin = (i * 256 + t) * 4;
        int row = lin >> 7, col = lin & 127;
        float4 v = make_float4(0.f, 0.f, 0.f, 0.f);
        if (row < valid_rows) {
            float dnm = g_denom[(size_t)(nb + row) * R + r];
            float s = 1.f / fmaxf(dnm, 1e-16f);
            float4 g = *(const float4*)(src + (size_t)row * row_stride + col);
            v = make_float4(g.x * s, g.y * s, g.z * s, g.w * s);
        }
        uint32_t off = (uint32_t)row * ROWB + (uint32_t)col * 2;
        __half h0 = __float2half_rn(v.x), h1 = __float2half_rn(v.y);
        __half h2 = __float2half_rn(v.z), h3 = __float2half_rn(v.w);
        uint32_t a = (uint32_t)__half_as_ushort(h0) | ((uint32_t)__half_as_ushort(h1) << 16);
        uint32_t b = (uint32_t)__half_as_ushort(h2) | ((uint32_t)__half_as_ushort(h3) << 16);
        asm volatile("st.shared.v2.u32 [%0], {%1,%2};" :: "r"(dstb + off), "r"(a), "r"(b));
    }
}

// M=64 per-warp compute: 16 rows x 64 cols, acc[8][4], bh loaded per 16-col group
__device__ __forceinline__ void compute_m64(uint32_t xb, uint32_t wb,
                                            int wm, int wn, int lane,
                                            float acc[8][4]) {
#pragma unroll
    for (int ks = 0; ks < 8; ks++) {
        int k0 = ks * 16;
        uint32_t ah[4];
        {
            uint32_t off = (uint32_t)(wm + (lane & 15)) * ROWB
                         + (uint32_t)(k0 + (lane >> 4) * 8) * 2;
            ldsm4(ah, xb + off);
        }
#pragma unroll
        for (int nb2 = 0; nb2 < 4; nb2++) {
            uint32_t bh[4];
            uint32_t off = (uint32_t)(k0 + ((lane >> 3) & 1) * 8 + (lane & 7)) * ROWB
                         + (uint32_t)(wn + nb2 * 16 + (lane >> 4) * 8) * 2;
            ldsm4t(bh, wb + off);
            mma16816(acc[nb2 * 2 + 0], ah, &bh[0]);
            mma16816(acc[nb2 * 2 + 1], ah, &bh[2]);
        }
    }
}

// ---------------- small kernels ----------------
__global__ void zero_kernel() {
    size_t i = (size_t)blockIdx.x * blockDim.x + threadIdx.x;
    size_t stride = (size_t)gridDim.x * blockDim.x;
    float4 z = make_float4(0.f, 0.f, 0.f, 0.f);
    float4* g4 = (float4*)g_G;
    size_t n4 = NRD / 4;
    for (size_t k = i; k < n4; k += stride) g4[k] = z;
    for (size_t k = i; k < (size_t)NR; k += stride) g_denom[k] = 0.f;
}

// parallel prep
__global__ void prep_kernel(const float* __restrict__ W_Q, const float* __restrict__ b_Q,
                            const float* __restrict__ W_K, const float* __restrict__ b_K,
                            const float* __restrict__ a_w, const float* __restrict__ a_b) {
    int w = blockIdx.x * 8 + (threadIdx.x >> 5);
    int l = threadIdx.x & 31;
    if (w < 512) {
        int r = w >> 7, d = w & 127;
        const float* wq = W_Q + ((size_t)(r * D + d)) * D;
        const float* wk = W_K + ((size_t)(r * D + d)) * D;
        float s = 0.f;
#pragma unroll
        for (int o = l; o < D; o += 32) s += wq[o] * a_w[o] + wk[o] * a_w[D + o];
#pragma unroll
        for (int off = 16; off; off >>= 1) s += __shfl_xor_sync(0xFFFFFFFFu, s, off);
        if (l == 0) g_wqk[w] = s;
    } else if (w < 516) {
        int r = w - 512;
        float c = 0.f;
#pragma unroll
        for (int o = l; o < D; o += 32)
            c += b_Q[r * D + o] * a_w[o] + b_K[r * D + o] * a_w[D + o];
#pragma unroll
        for (int off = 16; off; off >>= 1) c += __shfl_xor_sync(0xFFFFFFFFu, c, off);
        if (l == 0) g_c[r] = c + a_b[0];
    }
}

// FUSED edge pass with fp16 A/B gathers
__global__ void edge_fused_kernel(const int* __restrict__ ei, const int* __restrict__ et) {
    int e = blockIdx.x * 8 + (threadIdx.x >> 5);
    if (e >= N_EDGES) return;
    int l = threadIdx.x & 31;
    int src = ei[e], tgt = ei[N_EDGES + e], r = et[e];

    const __half2* Ap = (const __half2*)(g_A + ((size_t)src * R + r) * D) + l * 2;
    const __half2* Bp = (const __half2*)(g_B + ((size_t)tgt * R + r) * D) + l * 2;
    __half2 a01 = Ap[0], a23 = Ap[1];
    __half2 b01 = Bp[0], b23 = Bp[1];
    float2 af0 = __half22float2(a01), af1 = __half22float2(a23);
    float2 bf0 = __half22float2(b01), bf1 = __half22float2(b23);
    float4 rt;
    rt.x = lrelu(af0.x + bf0.x);
    rt.y = lrelu(af0.y + bf0.y);
    rt.z = lrelu(af1.x + bf1.x);
    rt.w = lrelu(af1.y + bf1.y);

    float4 w = ((const float4*)(g_wqk + r * D))[l];
    float p = rt.x * w.x + rt.y * w.y + rt.z * w.z + rt.w * w.w;
#pragma unroll
    for (int off = 16; off; off >>= 1) p += __shfl_xor_sync(0xFFFFFFFFu, p, off);

    float s = lrelu(p + g_c[r]);
    float ex = expf(fminf(s, 60.f));

    size_t seg = (size_t)tgt * R + r;
    if (l == 0) atomicAdd(&g_denom[seg], ex);

    float* dst = g_G + seg * D + l * 4;
    asm volatile("red.global.add.v4.f32 [%0], {%1,%2,%3,%4};"
                 :: "l"(dst), "f"(rt.x * ex), "f"(rt.y * ex),
                    "f"(rt.z * ex), "f"(rt.w * ex) : "memory");
}

// ---------------- GEMM kernels ----------------

// gemm_ab: M=64 tiles, 4 CTAs/SM
__global__ void __launch_bounds__(256, 4) gemm_ab_mma(const float* __restrict__ x,
                                                      const float* __restrict__ W_R,
                                                      const float* __restrict__ b_R) {
    extern __shared__ char sm[];
    uint32_t sb = smem_u32(sm);
    uint32_t xb = sb, wb = sb + GTILE_BYTES;
    int t = threadIdx.x, lane = t & 31, wid = t >> 5;
    int nb = blockIdx.x * 64;
    int wm = (wid >> 1) * 16, wn = (wid & 1) * 64;

    stage_x64(xb, x + (size_t)nb * D, D, N_NODES - nb, t);

    for (int rc = 0; rc < 8; rc++) {
        int r = rc & 3, which = rc >> 2;
        __syncthreads();   // prior compute done reading W; x staged (rc=0)
        stage_f16(wb, W_R + ((size_t)r * 2 * D + which * D) * D, D, 128, t);
        __syncthreads();

        float acc[8][4];
#pragma unroll
        for (int b = 0; b < 8; b++)
#pragma unroll
            for (int c = 0; c < 4; c++) acc[b][c] = 0.f;

        compute_m64(xb, wb, wm, wn, lane, acc);

        __half* outp = which ? g_B : g_A;
#pragma unroll
        for (int half = 0; half < 2; half++) {
            int row = nb + wm + (lane >> 2) + half * 8;
            if (row >= N_NODES) continue;
#pragma unroll
            for (int nt = 0; nt < 8; nt++) {
                int col = wn + nt * 8 + (lane & 3) * 2;
                float b0 = 0.f, b1 = 0.f;
                if (!which) { b0 = b_R[r * D + col]; b1 = b_R[r * D + col + 1]; }
                __half2 v = __floats2half2_rn(acc[nt][half * 2 + 0] + b0,
                                              acc[nt][half * 2 + 1] + b1);
                *(__half2*)(outp + ((size_t)row * R + r) * D + col) = v;
            }
        }
    }
}

// final: M=64 tiles, single G pass, 4 CTAs/SM
__global__ void __launch_bounds__(256, 4) final_mma(const float* __restrict__ W_V,
                                                    const float* __restrict__ b_V,
                                                    float* __restrict__ out) {
    extern __shared__ char sm[];
    uint32_t sb = smem_u32(sm);
    uint32_t gb = sb, wb = sb + GTILE_BYTES;
    int t = threadIdx.x, lane = t & 31, wid = t >> 5;
    int nb = blockIdx.x * 64;
    int wm = (wid >> 1) * 16, wn = (wid & 1) * 64;

    float acc[8][4];
#pragma unroll
    for (int b = 0; b < 8; b++)
#pragma unroll
        for (int c = 0; c < 4; c++) acc[b][c] = 0.f;

    for (int r = 0; r < R; r++) {
        __syncthreads();
        stage_g64(gb, g_G + ((size_t)nb * R + r) * D, (size_t)R * D,
                  N_NODES - nb, t, nb, r);
        stage_f16(wb, W_V + (size_t)r * D * D, D, 128, t);
        __syncthreads();
        compute_m64(gb, wb, wm, wn, lane, acc);
    }

#pragma unroll
    for (int half = 0; half < 2; half++) {
        int row = nb + wm + (lane >> 2) + half * 8;
        if (row >= N_NODES) continue;
        float4 dn = ((const float4*)g_denom)[row];
        float m0 = dn.x > 0.f ? 1.f : 0.f;
        float m1 = dn.y > 0.f ? 1.f : 0.f;
        float m2 = dn.z > 0.f ? 1.f : 0.f;
        float m3 = dn.w > 0.f ? 1.f : 0.f;
#pragma unroll
        for (int nt = 0; nt < 8; nt++) {
            int col = wn + nt * 8 + (lane & 3) * 2;
            float bias0 = m0 * b_V[col] + m1 * b_V[D + col]
                        + m2 * b_V[2 * D + col] + m3 * b_V[3 * D + col];
            float bias1 = m0 * b_V[col + 1] + m1 * b_V[D + col + 1]
                        + m2 * b_V[2 * D + col + 1] + m3 * b_V[3 * D + col + 1];
            float v0 = acc[nt][half * 2 + 0] + bias0;
            float v1 = acc[nt][half * 2 + 1] + bias1;
            float2 o2;
            o2.x = v0 > 0.f ? v0 : expm1f(v0);
            o2.y = v1 > 0.f ? v1 : expm1f(v1);
            *(float2*)(out + (size_t)row * D + col) = o2;
        }
    }
}

// ---------------- launch ----------------
extern "C" void kernel_launch(void* const* d_in, const int* in_sizes, int n_in,
                              void* d_out, int out_size) {
    const float* x   = (const float*)d_in[0];
    const int*   ei  = (const int*)d_in[1];
    const int*   et  = (const int*)d_in[2];
    const float* W_R = (const float*)d_in[3];
    const float* b_R = (const float*)d_in[4];
    const float* W_Q = (const float*)d_in[5];
    const float* b_Q = (const float*)d_in[6];
    const float* W_K = (const float*)d_in[7];
    const float* b_K = (const float*)d_in[8];
    const float* W_V = (const float*)d_in[9];
    const float* b_V = (const float*)d_in[10];
    const float* a_w = (const float*)d_in[11];
    const float* a_b = (const float*)d_in[12];
    float* out = (float*)d_out;

    static int smem_set = 0;
    if (!smem_set) {
        cudaFuncSetAttribute(gemm_ab_mma, cudaFuncAttributeMaxDynamicSharedMemorySize, GEMM_SMEM);
        cudaFuncSetAttribute(final_mma, cudaFuncAttributeMaxDynamicSharedMemorySize, FINAL_SMEM);
        smem_set = 1;
    }

    prep_kernel<<<65, 256>>>(W_Q, b_Q, W_K, b_K, a_w, a_b);
    zero_kernel<<<4096, 256>>>();

    gemm_ab_mma<<<(N_NODES + 63) / 64, 256, GEMM_SMEM>>>(x, W_R, b_R);

    edge_fused_kernel<<<N_EDGES / 8, 256>>>(ei, et);

    final_mma<<<(N_NODES + 63) / 64, 256, FINAL_SMEM>>>(W_V, b_V, out);
}

// round 15
// speedup vs baseline: 1.2211x; 1.2211x over previous
#include <cuda_runtime.h>
#include <cuda_fp16.h>
#include <cstdint>

#define N_NODES 100000
#define N_EDGES 640000
#define D 128
#define R 4
#define LRELU_ALPHA 0.2f

#define NR (N_NODES * R)
#define NRD ((size_t)N_NODES * R * D)
#define XD  ((size_t)N_NODES * D)

// ---------------- scratch ----------------
__device__ __align__(16) __half   g_A[NRD];
__device__ __align__(16) __half   g_B[NRD];
__device__ __align__(16) float    g_G[NRD];
__device__             float    g_denom[NR];
__device__ __align__(16) float    g_wqk[R * D];
__device__             float    g_c[R];
__device__ __align__(16) __half   g_xh[XD];                 // fp16 x
__device__ __align__(16) __half   g_wrh[(size_t)R * 2 * D * D]; // fp16 W_R (8 tiles, layout [r][which])
__device__ __align__(16) __half   g_wvh[(size_t)R * D * D];     // fp16 W_V (4 tiles)

// ---------------- helpers ----------------
__device__ __forceinline__ float lrelu(float v) { return v > 0.f ? v : LRELU_ALPHA * v; }
__device__ __forceinline__ uint32_t smem_u32(const void* p) {
    uint32_t a;
    asm("{ .reg .u64 t; cvta.to.shared.u64 t, %1; cvt.u32.u64 %0, t; }" : "=r"(a) : "l"(p));
    return a;
}

// ---------------- mma.sync primitives ----------------
__device__ __forceinline__ void ldsm4(uint32_t* r, uint32_t a) {
    asm volatile("ldmatrix.sync.aligned.m8n8.x4.shared.b16 {%0,%1,%2,%3}, [%4];"
                 : "=r"(r[0]), "=r"(r[1]), "=r"(r[2]), "=r"(r[3]) : "r"(a));
}
__device__ __forceinline__ void ldsm4t(uint32_t* r, uint32_t a) {
    asm volatile("ldmatrix.sync.aligned.m8n8.x4.trans.shared.b16 {%0,%1,%2,%3}, [%4];"
                 : "=r"(r[0]), "=r"(r[1]), "=r"(r[2]), "=r"(r[3]) : "r"(a));
}
__device__ __forceinline__ void mma16816(float* d, const uint32_t* a, const uint32_t* b) {
    asm volatile(
        "mma.sync.aligned.m16n8k16.row.col.f32.f16.f16.f32 "
        "{%0,%1,%2,%3}, {%4,%5,%6,%7}, {%8,%9}, {%0,%1,%2,%3};"
        : "+f"(d[0]), "+f"(d[1]), "+f"(d[2]), "+f"(d[3])
        : "r"(a[0]), "r"(a[1]), "r"(a[2]), "r"(a[3]), "r"(b[0]), "r"(b[1]));
}

#define ROWB 272
#define TILE_BYTES (128 * ROWB)
#define GTILE_BYTES (64 * ROWB)
#define GEMM_SMEM (2 * TILE_BYTES)            // x128 + W (69.6 KB -> 3 CTAs/SM)
#define FINAL_SMEM (GTILE_BYTES + TILE_BYTES) // g64 + W (52.2 KB -> 4 CTAs/SM)

#define CP_COMMIT() asm volatile("cp.async.commit_group;" ::: "memory")
#define CP_WAIT0()  asm volatile("cp.async.wait_group 0;" ::: "memory")

// cp.async-stage a 128x128 fp16 tile (rows contiguous 256B in gmem -> ROWB-stride smem)
__device__ __forceinline__ void stage_cp_w(uint32_t dstb, const __half* __restrict__ src, int t) {
#pragma unroll
    for (int i = 0; i < 8; i++) {
        int chunk = i * 256 + t;
        int row = chunk >> 4, k = chunk & 15;
        asm volatile("cp.async.cg.shared.global [%0], [%1], 16;"
                     :: "r"(dstb + (uint32_t)row * ROWB + (uint32_t)k * 16),
                        "l"(src + (size_t)row * D + k * 8) : "memory");
    }
    CP_COMMIT();
}

// cp.async-stage 128 rows of fp16 x with row bound (zero-fill out of range)
__device__ __forceinline__ void stage_cp_x(uint32_t dstb, const __half* __restrict__ src,
                                           int valid_rows, int t) {
#pragma unroll
    for (int i = 0; i < 8; i++) {
        int chunk = i * 256 + t;
        int row = chunk >> 4, k = chunk & 15;
        int ok = row < valid_rows;
        const __half* s = src + (size_t)(ok ? row : 0) * D + k * 8;
        int sz = ok ? 16 : 0;
        asm volatile("cp.async.cg.shared.global [%0], [%1], 16, %2;"
                     :: "r"(dstb + (uint32_t)row * ROWB + (uint32_t)k * 16),
                        "l"(s), "r"(sz) : "memory");
    }
    CP_COMMIT();
}

// stage 64x128 G rows scaled by 1/denom into fp16 buffer (sync loads)
__device__ __forceinline__ void stage_g64(uint32_t dstb, const float* __restrict__ src,
                                          size_t row_stride, int valid_rows, int t,
                                          int nb, int r) {
#pragma unroll
    for (int i = 0; i < 8; i++) {
        int lin = (i * 256 + t) * 4;
        int row = lin >> 7, col = lin & 127;
        float4 v = make_float4(0.f, 0.f, 0.f, 0.f);
        if (row < valid_rows) {
            float dnm = g_denom[(size_t)(nb + row) * R + r];
            float s = 1.f / fmaxf(dnm, 1e-16f);
            float4 g = *(const float4*)(src + (size_t)row * row_stride + col);
            v = make_float4(g.x * s, g.y * s, g.z * s, g.w * s);
        }
        uint32_t off = (uint32_t)row * ROWB + (uint32_t)col * 2;
        __half h0 = __float2half_rn(v.x), h1 = __float2half_rn(v.y);
        __half h2 = __float2half_rn(v.z), h3 = __float2half_rn(v.w);
        uint32_t a = (uint32_t)__half_as_ushort(h0) | ((uint32_t)__half_as_ushort(h1) << 16);
        uint32_t b = (uint32_t)__half_as_ushort(h2) | ((uint32_t)__half_as_ushort(h3) << 16);
        asm volatile("st.shared.v2.u32 [%0], {%1,%2};" :: "r"(dstb + off), "r"(a), "r"(b));
    }
}

// half-width pass: warp computes 32 rows x 32 cols (acc = 32 regs)  [gemm_ab]
__device__ __forceinline__ void compute_half(uint32_t xb, uint32_t wb,
                                             int wm, int cbase, int lane,
                                             float acc[2][4][4]) {
#pragma unroll
    for (int ks = 0; ks < 8; ks++) {
        int k0 = ks * 16;
        uint32_t ah[2][4];
#pragma unroll
        for (int mt = 0; mt < 2; mt++) {
            uint32_t off = (uint32_t)(wm + mt * 16 + (lane & 15)) * ROWB
                         + (uint32_t)(k0 + (lane >> 4) * 8) * 2;
            ldsm4(ah[mt], xb + off);
        }
        uint32_t bh[2][4];
#pragma unroll
        for (int nb2 = 0; nb2 < 2; nb2++) {
            uint32_t off = (uint32_t)(k0 + ((lane >> 3) & 1) * 8 + (lane & 7)) * ROWB
                         + (uint32_t)(cbase + nb2 * 16 + (lane >> 4) * 8) * 2;
            ldsm4t(bh[nb2], wb + off);
        }
#pragma unroll
        for (int mt = 0; mt < 2; mt++)
#pragma unroll
            for (int nt = 0; nt < 4; nt++)
                mma16816(acc[mt][nt], ah[mt], &bh[nt >> 1][(nt & 1) * 2]);
    }
}

// M=64 per-warp compute: 16 rows x 64 cols  [final]
__device__ __forceinline__ void compute_m64(uint32_t xb, uint32_t wb,
                                            int wm, int wn, int lane,
                                            float acc[8][4]) {
#pragma unroll
    for (int ks = 0; ks < 8; ks++) {
        int k0 = ks * 16;
        uint32_t ah[4];
        {
            uint32_t off = (uint32_t)(wm + (lane & 15)) * ROWB
                         + (uint32_t)(k0 + (lane >> 4) * 8) * 2;
            ldsm4(ah, xb + off);
        }
#pragma unroll
        for (int nb2 = 0; nb2 < 4; nb2++) {
            uint32_t bh[4];
            uint32_t off = (uint32_t)(k0 + ((lane >> 3) & 1) * 8 + (lane & 7)) * ROWB
                         + (uint32_t)(wn + nb2 * 16 + (lane >> 4) * 8) * 2;
            ldsm4t(bh, wb + off);
            mma16816(acc[nb2 * 2 + 0], ah, &bh[0]);
            mma16816(acc[nb2 * 2 + 1], ah, &bh[2]);
        }
    }
}

// ---------------- small kernels ----------------
// zero scratch + pre-convert x/W_R/W_V to fp16
__global__ void zero_convert_kernel(const float* __restrict__ x,
                                    const float* __restrict__ W_R,
                                    const float* __restrict__ W_V) {
    size_t i = (size_t)blockIdx.x * blockDim.x + threadIdx.x;
    size_t stride = (size_t)gridDim.x * blockDim.x;
    float4 z = make_float4(0.f, 0.f, 0.f, 0.f);
    float4* g4 = (float4*)g_G;
    size_t n4 = NRD / 4;
    for (size_t k = i; k < n4; k += stride) g4[k] = z;
    for (size_t k = i; k < (size_t)NR; k += stride) g_denom[k] = 0.f;
    __half2* xh2 = (__half2*)g_xh;
    for (size_t k = i; k < XD / 4; k += stride) {
        float4 v = ((const float4*)x)[k];
        xh2[k * 2]     = __floats2half2_rn(v.x, v.y);
        xh2[k * 2 + 1] = __floats2half2_rn(v.z, v.w);
    }
    __half2* wr2 = (__half2*)g_wrh;
    const size_t WR4 = (size_t)R * 2 * D * D / 4;
    for (size_t k = i; k < WR4; k += stride) {
        float4 v = ((const float4*)W_R)[k];
        wr2[k * 2]     = __floats2half2_rn(v.x, v.y);
        wr2[k * 2 + 1] = __floats2half2_rn(v.z, v.w);
    }
    __half2* wv2 = (__half2*)g_wvh;
    const size_t WV4 = (size_t)R * D * D / 4;
    for (size_t k = i; k < WV4; k += stride) {
        float4 v = ((const float4*)W_V)[k];
        wv2[k * 2]     = __floats2half2_rn(v.x, v.y);
        wv2[k * 2 + 1] = __floats2half2_rn(v.z, v.w);
    }
}

// parallel prep
__global__ void prep_kernel(const float* __restrict__ W_Q, const float* __restrict__ b_Q,
                            const float* __restrict__ W_K, const float* __restrict__ b_K,
                            const float* __restrict__ a_w, const float* __restrict__ a_b) {
    int w = blockIdx.x * 8 + (threadIdx.x >> 5);
    int l = threadIdx.x & 31;
    if (w < 512) {
        int r = w >> 7, d = w & 127;
        const float* wq = W_Q + ((size_t)(r * D + d)) * D;
        const float* wk = W_K + ((size_t)(r * D + d)) * D;
        float s = 0.f;
#pragma unroll
        for (int o = l; o < D; o += 32) s += wq[o] * a_w[o] + wk[o] * a_w[D + o];
#pragma unroll
        for (int off = 16; off; off >>= 1) s += __shfl_xor_sync(0xFFFFFFFFu, s, off);
        if (l == 0) g_wqk[w] = s;
    } else if (w < 516) {
        int r = w - 512;
        float c = 0.f;
#pragma unroll
        for (int o = l; o < D; o += 32)
            c += b_Q[r * D + o] * a_w[o] + b_K[r * D + o] * a_w[D + o];
#pragma unroll
        for (int off = 16; off; off >>= 1) c += __shfl_xor_sync(0xFFFFFFFFu, c, off);
        if (l == 0) g_c[r] = c + a_b[0];
    }
}

// FUSED edge pass with fp16 A/B gathers
__global__ void edge_fused_kernel(const int* __restrict__ ei, const int* __restrict__ et) {
    int e = blockIdx.x * 8 + (threadIdx.x >> 5);
    if (e >= N_EDGES) return;
    int l = threadIdx.x & 31;
    int src = ei[e], tgt = ei[N_EDGES + e], r = et[e];

    const __half2* Ap = (const __half2*)(g_A + ((size_t)src * R + r) * D) + l * 2;
    const __half2* Bp = (const __half2*)(g_B + ((size_t)tgt * R + r) * D) + l * 2;
    __half2 a01 = Ap[0], a23 = Ap[1];
    __half2 b01 = Bp[0], b23 = Bp[1];
    float2 af0 = __half22float2(a01), af1 = __half22float2(a23);
    float2 bf0 = __half22float2(b01), bf1 = __half22float2(b23);
    float4 rt;
    rt.x = lrelu(af0.x + bf0.x);
    rt.y = lrelu(af0.y + bf0.y);
    rt.z = lrelu(af1.x + bf1.x);
    rt.w = lrelu(af1.y + bf1.y);

    float4 w = ((const float4*)(g_wqk + r * D))[l];
    float p = rt.x * w.x + rt.y * w.y + rt.z * w.z + rt.w * w.w;
#pragma unroll
    for (int off = 16; off; off >>= 1) p += __shfl_xor_sync(0xFFFFFFFFu, p, off);

    float s = lrelu(p + g_c[r]);
    float ex = expf(fminf(s, 60.f));

    size_t seg = (size_t)tgt * R + r;
    if (l == 0) atomicAdd(&g_denom[seg], ex);

    float* dst = g_G + seg * D + l * 4;
    asm volatile("red.global.add.v4.f32 [%0], {%1,%2,%3,%4};"
                 :: "l"(dst), "f"(rt.x * ex), "f"(rt.y * ex),
                    "f"(rt.z * ex), "f"(rt.w * ex) : "memory");
}

// ---------------- GEMM kernels ----------------

// gemm_ab: M=128 tiles, 3 CTAs/SM, cp.async staging from pre-converted fp16
__global__ void __launch_bounds__(256, 3) gemm_ab_mma(const float* __restrict__ b_R) {
    extern __shared__ char sm[];
    uint32_t sb = smem_u32(sm);
    uint32_t xb = sb, wb = sb + TILE_BYTES;
    int t = threadIdx.x, lane = t & 31, wid = t >> 5;
    int nb = blockIdx.x * 128;
    int wm = (wid >> 1) * 32, wn = (wid & 1) * 64;

    stage_cp_x(xb, g_xh + (size_t)nb * D, N_NODES - nb, t);

    for (int rc = 0; rc < 8; rc++) {
        int r = rc & 3, which = rc >> 2;
        __syncthreads();   // prior compute done reading W
        // W_R layout: [r][which] -> tile offset (r*2 + which)  (FIXED from R14)
        stage_cp_w(wb, g_wrh + (size_t)(r * 2 + which) * D * D, t);
        CP_WAIT0();
        __syncthreads();

        __half* outp = which ? g_B : g_A;
#pragma unroll
        for (int nh = 0; nh < 2; nh++) {
            int cbase = wn + nh * 32;
            float acc[2][4][4];
#pragma unroll
            for (int a = 0; a < 2; a++)
#pragma unroll
                for (int b = 0; b < 4; b++)
#pragma unroll
                    for (int c = 0; c < 4; c++) acc[a][b][c] = 0.f;

            compute_half(xb, wb, wm, cbase, lane, acc);

#pragma unroll
            for (int mt = 0; mt < 2; mt++) {
                int row0 = nb + wm + mt * 16 + (lane >> 2);
                int row1 = row0 + 8;
#pragma unroll
                for (int nt = 0; nt < 4; nt++) {
                    int col = cbase + nt * 8 + (lane & 3) * 2;
                    float b0 = 0.f, b1 = 0.f;
                    if (!which) { b0 = b_R[r * D + col]; b1 = b_R[r * D + col + 1]; }
                    if (row0 < N_NODES) {
                        __half2 v = __floats2half2_rn(acc[mt][nt][0] + b0, acc[mt][nt][1] + b1);
                        *(__half2*)(outp + ((size_t)row0 * R + r) * D + col) = v;
                    }
                    if (row1 < N_NODES) {
                        __half2 v = __floats2half2_rn(acc[mt][nt][2] + b0, acc[mt][nt][3] + b1);
                        *(__half2*)(outp + ((size_t)row1 * R + r) * D + col) = v;
                    }
                }
            }
        }
    }
}

// final: M=64 tiles, single G pass, 4 CTAs/SM, W via cp.async
__global__ void __launch_bounds__(256, 4) final_mma(const float* __restrict__ b_V,
                                                    float* __restrict__ out) {
    extern __shared__ char sm[];
    uint32_t sb = smem_u32(sm);
    uint32_t gb = sb, wb = sb + GTILE_BYTES;
    int t = threadIdx.x, lane = t & 31, wid = t >> 5;
    int nb = blockIdx.x * 64;
    int wm = (wid >> 1) * 16, wn = (wid & 1) * 64;

    float acc[8][4];
#pragma unroll
    for (int b = 0; b < 8; b++)
#pragma unroll
        for (int c = 0; c < 4; c++) acc[b][c] = 0.f;

    for (int r = 0; r < R; r++) {
        __syncthreads();
        stage_cp_w(wb, g_wvh + (size_t)r * D * D, t);     // async; overlaps G staging
        stage_g64(gb, g_G + ((size_t)nb * R + r) * D, (size_t)R * D,
                  N_NODES - nb, t, nb, r);
        CP_WAIT0();
        __syncthreads();
        compute_m64(gb, wb, wm, wn, lane, acc);
    }

#pragma unroll
    for (int half = 0; half < 2; half++) {
        int row = nb + wm + (lane >> 2) + half * 8;
        if (row >= N_NODES) continue;
        float4 dn = ((const float4*)g_denom)[row];
        float m0 = dn.x > 0.f ? 1.f : 0.f;
        float m1 = dn.y > 0.f ? 1.f : 0.f;
        float m2 = dn.z > 0.f ? 1.f : 0.f;
        float m3 = dn.w > 0.f ? 1.f : 0.f;
#pragma unroll
        for (int nt = 0; nt < 8; nt++) {
            int col = wn + nt * 8 + (lane & 3) * 2;
            float bias0 = m0 * b_V[col] + m1 * b_V[D + col]
                        + m2 * b_V[2 * D + col] + m3 * b_V[3 * D + col];
            float bias1 = m0 * b_V[col + 1] + m1 * b_V[D + col + 1]
                        + m2 * b_V[2 * D + col + 1] + m3 * b_V[3 * D + col + 1];
            float v0 = acc[nt][half * 2 + 0] + bias0;
            float v1 = acc[nt][half * 2 + 1] + bias1;
            float2 o2;
            o2.x = v0 > 0.f ? v0 : expm1f(v0);
            o2.y = v1 > 0.f ? v1 : expm1f(v1);
            *(float2*)(out + (size_t)row * D + col) = o2;
        }
    }
}

// ---------------- launch ----------------
extern "C" void kernel_launch(void* const* d_in, const int* in_sizes, int n_in,
                              void* d_out, int out_size) {
    const float* x   = (const float*)d_in[0];
    const int*   ei  = (const int*)d_in[1];
    const int*   et  = (const int*)d_in[2];
    const float* W_R = (const float*)d_in[3];
    const float* b_R = (const float*)d_in[4];
    const float* W_Q = (const float*)d_in[5];
    const float* b_Q = (const float*)d_in[6];
    const float* W_K = (const float*)d_in[7];
    const float* b_K = (const float*)d_in[8];
    const float* W_V = (const float*)d_in[9];
    const float* b_V = (const float*)d_in[10];
    const float* a_w = (const float*)d_in[11];
    const float* a_b = (const float*)d_in[12];
    float* out = (float*)d_out;

    static int smem_set = 0;
    if (!smem_set) {
        cudaFuncSetAttribute(gemm_ab_mma, cudaFuncAttributeMaxDynamicSharedMemorySize, GEMM_SMEM);
        cudaFuncSetAttribute(final_mma, cudaFuncAttributeMaxDynamicSharedMemorySize, FINAL_SMEM);
        smem_set = 1;
    }

    prep_kernel<<<65, 256>>>(W_Q, b_Q, W_K, b_K, a_w, a_b);
    zero_convert_kernel<<<4096, 256>>>(x, W_R, W_V);

    gemm_ab_mma<<<(N_NODES + 127) / 128, 256, GEMM_SMEM>>>(b_R);

    edge_fused_kernel<<<N_EDGES / 8, 256>>>(ei, et);

    final_mma<<<(N_NODES + 63) / 64, 256, FINAL_SMEM>>>(b_V, out);
}

// round 17
// speedup vs baseline: 1.2474x; 1.0215x over previous
#include <cuda_runtime.h>
#include <cuda_fp16.h>
#include <cstdint>

#define N_NODES 100000
#define N_EDGES 640000
#define D 128
#define R 4
#define LRELU_ALPHA 0.2f

#define NR (N_NODES * R)
#define NRD ((size_t)N_NODES * R * D)
#define XD  ((size_t)N_NODES * D)

// ---------------- scratch ----------------
__device__ __align__(16) __half   g_A[NRD];
__device__ __align__(16) __half   g_B[NRD];
__device__ __align__(16) float    g_G[NRD];
__device__             float    g_denom[NR];
__device__ __align__(16) float    g_wqk[R * D];
__device__             float    g_c[R];
__device__ __align__(16) __half   g_xh[XD];
__device__ __align__(16) __half   g_wrh[(size_t)R * 2 * D * D]; // layout [r][which]
__device__ __align__(16) __half   g_wvh[(size_t)R * D * D];

// ---------------- helpers ----------------
__device__ __forceinline__ float lrelu(float v) { return v > 0.f ? v : LRELU_ALPHA * v; }
__device__ __forceinline__ uint32_t smem_u32(const void* p) {
    uint32_t a;
    asm("{ .reg .u64 t; cvta.to.shared.u64 t, %1; cvt.u32.u64 %0, t; }" : "=r"(a) : "l"(p));
    return a;
}

// ---------------- mma.sync primitives ----------------
__device__ __forceinline__ void ldsm4(uint32_t* r, uint32_t a) {
    asm volatile("ldmatrix.sync.aligned.m8n8.x4.shared.b16 {%0,%1,%2,%3}, [%4];"
                 : "=r"(r[0]), "=r"(r[1]), "=r"(r[2]), "=r"(r[3]) : "r"(a));
}
__device__ __forceinline__ void ldsm4t(uint32_t* r, uint32_t a) {
    asm volatile("ldmatrix.sync.aligned.m8n8.x4.trans.shared.b16 {%0,%1,%2,%3}, [%4];"
                 : "=r"(r[0]), "=r"(r[1]), "=r"(r[2]), "=r"(r[3]) : "r"(a));
}
__device__ __forceinline__ void mma16816(float* d, const uint32_t* a, const uint32_t* b) {
    asm volatile(
        "mma.sync.aligned.m16n8k16.row.col.f32.f16.f16.f32 "
        "{%0,%1,%2,%3}, {%4,%5,%6,%7}, {%8,%9}, {%0,%1,%2,%3};"
        : "+f"(d[0]), "+f"(d[1]), "+f"(d[2]), "+f"(d[3])
        : "r"(a[0]), "r"(a[1]), "r"(a[2]), "r"(a[3]), "r"(b[0]), "r"(b[1]));
}

#define ROWB 272
#define TILE_BYTES (128 * ROWB)
#define GTILE_BYTES (64 * ROWB)
#define GEMM_SMEM (2 * TILE_BYTES)            // x128 + W -> 3 CTAs/SM
#define FINAL_SMEM (GTILE_BYTES + TILE_BYTES) // g64 + W -> 4 CTAs/SM

#define CP_COMMIT() asm volatile("cp.async.commit_group;" ::: "memory")
#define CP_WAIT0()  asm volatile("cp.async.wait_group 0;" ::: "memory")

// cp.async-stage a 128x128 fp16 tile
__device__ __forceinline__ void stage_cp_w(uint32_t dstb, const __half* __restrict__ src, int t) {
#pragma unroll
    for (int i = 0; i < 8; i++) {
        int chunk = i * 256 + t;
        int row = chunk >> 4, k = chunk & 15;
        asm volatile("cp.async.cg.shared.global [%0], [%1], 16;"
                     :: "r"(dstb + (uint32_t)row * ROWB + (uint32_t)k * 16),
                        "l"(src + (size_t)row * D + k * 8) : "memory");
    }
    CP_COMMIT();
}

// cp.async-stage 128 rows of fp16 x with row bound (zero-fill out of range)
__device__ __forceinline__ void stage_cp_x(uint32_t dstb, const __half* __restrict__ src,
                                           int valid_rows, int t) {
#pragma unroll
    for (int i = 0; i < 8; i++) {
        int chunk = i * 256 + t;
        int row = chunk >> 4, k = chunk & 15;
        int ok = row < valid_rows;
        const __half* s = src + (size_t)(ok ? row : 0) * D + k * 8;
        int sz = ok ? 16 : 0;
        asm volatile("cp.async.cg.shared.global [%0], [%1], 16, %2;"
                     :: "r"(dstb + (uint32_t)row * ROWB + (uint32_t)k * 16),
                        "l"(s), "r"(sz) : "memory");
    }
    CP_COMMIT();
}

// stage 64x128 G rows scaled by 1/denom into fp16 buffer (sync loads)
__device__ __forceinline__ void stage_g64(uint32_t dstb, const float* __restrict__ src,
                                          size_t row_stride, int valid_rows, int t,
                                          int nb, int r) {
#pragma unroll
    for (int i = 0; i < 8; i++) {
        int lin = (i * 256 + t) * 4;
        int row = lin >> 7, col = lin & 127;
        float4 v = make_float4(0.f, 0.f, 0.f, 0.f);
        if (row < valid_rows) {
            float dnm = g_denom[(size_t)(nb + row) * R + r];
            float s = 1.f / fmaxf(dnm, 1e-16f);
            float4 g = *(const float4*)(src + (size_t)row * row_stride + col);
            v = make_float4(g.x * s, g.y * s, g.z * s, g.w * s);
        }
        uint32_t off = (uint32_t)row * ROWB + (uint32_t)col * 2;
        __half h0 = __float2half_rn(v.x), h1 = __float2half_rn(v.y);
        __half h2 = __float2half_rn(v.z), h3 = __float2half_rn(v.w);
        uint32_t a = (uint32_t)__half_as_ushort(h0) | ((uint32_t)__half_as_ushort(h1) << 16);
        uint32_t b = (uint32_t)__half_as_ushort(h2) | ((uint32_t)__half_as_ushort(h3) << 16);
        asm volatile("st.shared.v2.u32 [%0], {%1,%2};" :: "r"(dstb + off), "r"(a), "r"(b));
    }
}

// half-width pass: warp computes 32 rows x 32 cols (acc = 32 regs)  [gemm_ab]
__device__ __forceinline__ void compute_half(uint32_t xb, uint32_t wb,
                                             int wm, int cbase, int lane,
                                             float acc[2][4][4]) {
#pragma unroll
    for (int ks = 0; ks < 8; ks++) {
        int k0 = ks * 16;
        uint32_t ah[2][4];
#pragma unroll
        for (int mt = 0; mt < 2; mt++) {
            uint32_t off = (uint32_t)(wm + mt * 16 + (lane & 15)) * ROWB
                         + (uint32_t)(k0 + (lane >> 4) * 8) * 2;
            ldsm4(ah[mt], xb + off);
        }
        uint32_t bh[2][4];
#pragma unroll
        for (int nb2 = 0; nb2 < 2; nb2++) {
            uint32_t off = (uint32_t)(k0 + ((lane >> 3) & 1) * 8 + (lane & 7)) * ROWB
                         + (uint32_t)(cbase + nb2 * 16 + (lane >> 4) * 8) * 2;
            ldsm4t(bh[nb2], wb + off);
        }
#pragma unroll
        for (int mt = 0; mt < 2; mt++)
#pragma unroll
            for (int nt = 0; nt < 4; nt++)
                mma16816(acc[mt][nt], ah[mt], &bh[nt >> 1][(nt & 1) * 2]);
    }
}

// M=64 per-warp compute: 16 rows x 64 cols  [final]
__device__ __forceinline__ void compute_m64(uint32_t xb, uint32_t wb,
                                            int wm, int wn, int lane,
                                            float acc[8][4]) {
#pragma unroll
    for (int ks = 0; ks < 8; ks++) {
        int k0 = ks * 16;
        uint32_t ah[4];
        {
            uint32_t off = (uint32_t)(wm + (lane & 15)) * ROWB
                         + (uint32_t)(k0 + (lane >> 4) * 8) * 2;
            ldsm4(ah, xb + off);
        }
#pragma unroll
        for (int nb2 = 0; nb2 < 4; nb2++) {
            uint32_t bh[4];
            uint32_t off = (uint32_t)(k0 + ((lane >> 3) & 1) * 8 + (lane & 7)) * ROWB
                         + (uint32_t)(wn + nb2 * 16 + (lane >> 4) * 8) * 2;
            ldsm4t(bh, wb + off);
            mma16816(acc[nb2 * 2 + 0], ah, &bh[0]);
            mma16816(acc[nb2 * 2 + 1], ah, &bh[2]);
        }
    }
}

// ---------------- small kernels ----------------
// convert x/W_R/W_V to fp16 (G/denom zeroing moved into gemm_ab prologue)
__global__ void convert_kernel(const float* __restrict__ x,
                               const float* __restrict__ W_R,
                               const float* __restrict__ W_V) {
    size_t i = (size_t)blockIdx.x * blockDim.x + threadIdx.x;
    size_t stride = (size_t)gridDim.x * blockDim.x;
    __half2* xh2 = (__half2*)g_xh;
    for (size_t k = i; k < XD / 4; k += stride) {
        float4 v = ((const float4*)x)[k];
        xh2[k * 2]     = __floats2half2_rn(v.x, v.y);
        xh2[k * 2 + 1] = __floats2half2_rn(v.z, v.w);
    }
    __half2* wr2 = (__half2*)g_wrh;
    const size_t WR4 = (size_t)R * 2 * D * D / 4;
    for (size_t k = i; k < WR4; k += stride) {
        float4 v = ((const float4*)W_R)[k];
        wr2[k * 2]     = __floats2half2_rn(v.x, v.y);
        wr2[k * 2 + 1] = __floats2half2_rn(v.z, v.w);
    }
    __half2* wv2 = (__half2*)g_wvh;
    const size_t WV4 = (size_t)R * D * D / 4;
    for (size_t k = i; k < WV4; k += stride) {
        float4 v = ((const float4*)W_V)[k];
        wv2[k * 2]     = __floats2half2_rn(v.x, v.y);
        wv2[k * 2 + 1] = __floats2half2_rn(v.z, v.w);
    }
}

// parallel prep
__global__ void prep_kernel(const float* __restrict__ W_Q, const float* __restrict__ b_Q,
                            const float* __restrict__ W_K, const float* __restrict__ b_K,
                            const float* __restrict__ a_w, const float* __restrict__ a_b) {
    int w = blockIdx.x * 8 + (threadIdx.x >> 5);
    int l = threadIdx.x & 31;
    if (w < 512) {
        int r = w >> 7, d = w & 127;
        const float* wq = W_Q + ((size_t)(r * D + d)) * D;
        const float* wk = W_K + ((size_t)(r * D + d)) * D;
        float s = 0.f;
#pragma unroll
        for (int o = l; o < D; o += 32) s += wq[o] * a_w[o] + wk[o] * a_w[D + o];
#pragma unroll
        for (int off = 16; off; off >>= 1) s += __shfl_xor_sync(0xFFFFFFFFu, s, off);
        if (l == 0) g_wqk[w] = s;
    } else if (w < 516) {
        int r = w - 512;
        float c = 0.f;
#pragma unroll
        for (int o = l; o < D; o += 32)
            c += b_Q[r * D + o] * a_w[o] + b_K[r * D + o] * a_w[D + o];
#pragma unroll
        for (int off = 16; off; off >>= 1) c += __shfl_xor_sync(0xFFFFFFFFu, c, off);
        if (l == 0) g_c[r] = c + a_b[0];
    }
}

// FUSED edge pass with fp16 A/B gathers, fp32 G scatter
__global__ void edge_fused_kernel(const int* __restrict__ ei, const int* __restrict__ et) {
    int e = blockIdx.x * 8 + (threadIdx.x >> 5);
    if (e >= N_EDGES) return;
    int l = threadIdx.x & 31;
    int src = ei[e], tgt = ei[N_EDGES + e], r = et[e];

    const __half2* Ap = (const __half2*)(g_A + ((size_t)src * R + r) * D) + l * 2;
    const __half2* Bp = (const __half2*)(g_B + ((size_t)tgt * R + r) * D) + l * 2;
    __half2 a01 = Ap[0], a23 = Ap[1];
    __half2 b01 = Bp[0], b23 = Bp[1];
    float2 af0 = __half22float2(a01), af1 = __half22float2(a23);
    float2 bf0 = __half22float2(b01), bf1 = __half22float2(b23);
    float4 rt;
    rt.x = lrelu(af0.x + bf0.x);
    rt.y = lrelu(af0.y + bf0.y);
    rt.z = lrelu(af1.x + bf1.x);
    rt.w = lrelu(af1.y + bf1.y);

    float4 w = ((const float4*)(g_wqk + r * D))[l];
    float p = rt.x * w.x + rt.y * w.y + rt.z * w.z + rt.w * w.w;
#pragma unroll
    for (int off = 16; off; off >>= 1) p += __shfl_xor_sync(0xFFFFFFFFu, p, off);

    float s = lrelu(p + g_c[r]);
    float ex = expf(fminf(s, 60.f));

    size_t seg = (size_t)tgt * R + r;
    if (l == 0) atomicAdd(&g_denom[seg], ex);

    float* dst = g_G + seg * D + l * 4;
    asm volatile("red.global.add.v4.f32 [%0], {%1,%2,%3,%4};"
                 :: "l"(dst), "f"(rt.x * ex), "f"(rt.y * ex),
                    "f"(rt.z * ex), "f"(rt.w * ex) : "memory");
}

// ---------------- GEMM kernels ----------------

// gemm_ab: M=128 tiles, 3 CTAs/SM; prologue zeroes G/denom (hidden under mma)
__global__ void __launch_bounds__(256, 3) gemm_ab_mma(const float* __restrict__ b_R) {
    extern __shared__ char sm[];
    uint32_t sb = smem_u32(sm);
    uint32_t xb = sb, wb = sb + TILE_BYTES;
    int t = threadIdx.x, lane = t & 31, wid = t >> 5;
    int nb = blockIdx.x * 128;
    int wm = (wid >> 1) * 32, wn = (wid & 1) * 64;

    stage_cp_x(xb, g_xh + (size_t)nb * D, N_NODES - nb, t);

    // zero G + denom (fire-and-forget streaming stores; drain under compute;
    // completion guaranteed by the kernel boundary before edge_fused)
    {
        size_t gi = (size_t)blockIdx.x * 256 + t;
        size_t gs = (size_t)gridDim.x * 256;
        float4 z = make_float4(0.f, 0.f, 0.f, 0.f);
        float4* g4 = (float4*)g_G;
        for (size_t k = gi; k < NRD / 4; k += gs) g4[k] = z;
        for (size_t k = gi; k < (size_t)NR; k += gs) g_denom[k] = 0.f;
    }

    for (int rc = 0; rc < 8; rc++) {
        int r = rc & 3, which = rc >> 2;
        __syncthreads();
        stage_cp_w(wb, g_wrh + (size_t)(r * 2 + which) * D * D, t);
        CP_WAIT0();
        __syncthreads();

        __half* outp = which ? g_B : g_A;
#pragma unroll
        for (int nh = 0; nh < 2; nh++) {
            int cbase = wn + nh * 32;
            float acc[2][4][4];
#pragma unroll
            for (int a = 0; a < 2; a++)
#pragma unroll
                for (int b = 0; b < 4; b++)
#pragma unroll
                    for (int c = 0; c < 4; c++) acc[a][b][c] = 0.f;

            compute_half(xb, wb, wm, cbase, lane, acc);

#pragma unroll
            for (int mt = 0; mt < 2; mt++) {
                int row0 = nb + wm + mt * 16 + (lane >> 2);
                int row1 = row0 + 8;
#pragma unroll
                for (int nt = 0; nt < 4; nt++) {
                    int col = cbase + nt * 8 + (lane & 3) * 2;
                    float b0 = 0.f, b1 = 0.f;
                    if (!which) { b0 = b_R[r * D + col]; b1 = b_R[r * D + col + 1]; }
                    if (row0 < N_NODES) {
                        __half2 v = __floats2half2_rn(acc[mt][nt][0] + b0, acc[mt][nt][1] + b1);
                        *(__half2*)(outp + ((size_t)row0 * R + r) * D + col) = v;
                    }
                    if (row1 < N_NODES) {
                        __half2 v = __floats2half2_rn(acc[mt][nt][2] + b0, acc[mt][nt][3] + b1);
                        *(__half2*)(outp + ((size_t)row1 * R + r) * D + col) = v;
                    }
                }
            }
        }
    }
}

// final: M=64 tiles, single G pass, 4 CTAs/SM, W via cp.async
__global__ void __launch_bounds__(256, 4) final_mma(const float* __restrict__ b_V,
                                                    float* __restrict__ out) {
    extern __shared__ char sm[];
    uint32_t sb = smem_u32(sm);
    uint32_t gb = sb, wb = sb + GTILE_BYTES;
    int t = threadIdx.x, lane = t & 31, wid = t >> 5;
    int nb = blockIdx.x * 64;
    int wm = (wid >> 1) * 16, wn = (wid & 1) * 64;

    float acc[8][4];
#pragma unroll
    for (int b = 0; b < 8; b++)
#pragma unroll
        for (int c = 0; c < 4; c++) acc[b][c] = 0.f;

    for (int r = 0; r < R; r++) {
        __syncthreads();
        stage_cp_w(wb, g_wvh + (size_t)r * D * D, t);     // async; overlaps G staging
        stage_g64(gb, g_G + ((size_t)nb * R + r) * D, (size_t)R * D,
                  N_NODES - nb, t, nb, r);
        CP_WAIT0();
        __syncthreads();
        compute_m64(gb, wb, wm, wn, lane, acc);
    }

#pragma unroll
    for (int half = 0; half < 2; half++) {
        int row = nb + wm + (lane >> 2) + half * 8;
        if (row >= N_NODES) continue;
        float4 dn = ((const float4*)g_denom)[row];
        float m0 = dn.x > 0.f ? 1.f : 0.f;
        float m1 = dn.y > 0.f ? 1.f : 0.f;
        float m2 = dn.z > 0.f ? 1.f : 0.f;
        float m3 = dn.w > 0.f ? 1.f : 0.f;
#pragma unroll
        for (int nt = 0; nt < 8; nt++) {
            int col = wn + nt * 8 + (lane & 3) * 2;
            float bias0 = m0 * b_V[col] + m1 * b_V[D + col]
                        + m2 * b_V[2 * D + col] + m3 * b_V[3 * D + col];
            float bias1 = m0 * b_V[col + 1] + m1 * b_V[D + col + 1]
                        + m2 * b_V[2 * D + col + 1] + m3 * b_V[3 * D + col + 1];
            float v0 = acc[nt][half * 2 + 0] + bias0;
            float v1 = acc[nt][half * 2 + 1] + bias1;
            float2 o2;
            o2.x = v0 > 0.f ? v0 : expm1f(v0);
            o2.y = v1 > 0.f ? v1 : expm1f(v1);
            *(float2*)(out + (size_t)row * D + col) = o2;
        }
    }
}

// ---------------- launch ----------------
extern "C" void kernel_launch(void* const* d_in, const int* in_sizes, int n_in,
                              void* d_out, int out_size) {
    const float* x   = (const float*)d_in[0];
    const int*   ei  = (const int*)d_in[1];
    const int*   et  = (const int*)d_in[2];
    const float* W_R = (const float*)d_in[3];
    const float* b_R = (const float*)d_in[4];
    const float* W_Q = (const float*)d_in[5];
    const float* b_Q = (const float*)d_in[6];
    const float* W_K = (const float*)d_in[7];
    const float* b_K = (const float*)d_in[8];
    const float* W_V = (const float*)d_in[9];
    const float* b_V = (const float*)d_in[10];
    const float* a_w = (const float*)d_in[11];
    const float* a_b = (const float*)d_in[12];
    float* out = (float*)d_out;

    static int smem_set = 0;
    if (!smem_set) {
        cudaFuncSetAttribute(gemm_ab_mma, cudaFuncAttributeMaxDynamicSharedMemorySize, GEMM_SMEM);
        cudaFuncSetAttribute(final_mma, cudaFuncAttributeMaxDynamicSharedMemorySize, FINAL_SMEM);
        smem_set = 1;
    }

    prep_kernel<<<65, 256>>>(W_Q, b_Q, W_K, b_K, a_w, a_b);
    convert_kernel<<<2048, 256>>>(x, W_R, W_V);

    gemm_ab_mma<<<(N_NODES + 127) / 128, 256, GEMM_SMEM>>>(b_R);

    edge_fused_kernel<<<N_EDGES / 8, 256>>>(ei, et);

    final_mma<<<(N_NODES + 63) / 64, 256, FINAL_SMEM>>>(b_V, out);
}